// round 6
// baseline (speedup 1.0000x reference)
#include <cuda_runtime.h>

#define NROWS 512
#define DDIM  512
#define NTILE 16          // 512/32 tiles per dim
#define UPPER_TILES 136   // NTILE*(NTILE+1)/2  == grid size (< 148 SMs: co-resident)

// Scratch (allocation-free rule: __device__ globals)
__device__ float g_dot[NROWS * NROWS];  // raw dot products (upper triangle + diag)
__device__ float g_inv[NROWS];          // 1/max(norm,eps), from diagonal tiles
__device__ int   g_idx32;               // 1 if indices buffer is int32, 0 if int64
__device__ int   g_bar  = 0;            // phase barrier (reset each call)
__device__ int   g_done = 0;            // completion counter (reset each call)

// ---------------------------------------------------------------------------
// Fused persistent kernel. 136 blocks x 256 threads, one wave.
// Phase 1: upper-triangle dot GEMM (32x32 tile, 2x2 micro-tile).
// Device-wide spin barrier (safe: all 136 blocks co-resident).
// Phase 2: warp-per-anchor triplet sum (blocks 0..63 only).
// Last-finisher resets barrier counters for graph replay.
// ---------------------------------------------------------------------------
__global__ void fused_kernel(const float* __restrict__ embs,
                             const void* __restrict__ idxraw,
                             float* __restrict__ out) {
    const int tid = threadIdx.x;          // 0..255
    const int bid = blockIdx.x;

    // ======================= Phase 1: GEMM =======================
    {
        // Decode linear block id -> (by, bx) with bx >= by
        int rem = bid;
        int by = 0;
        while (rem >= NTILE - by) { rem -= NTILE - by; by++; }
        const int bx = by + rem;

        const int tx = tid & 15;
        const int ty = tid >> 4;

        __shared__ float Ash[32][34];     // [k][m], pad 34: float2-aligned + conflict-free
        __shared__ float Bsh[32][34];

        float a00 = 0.f, a01 = 0.f, a10 = 0.f, a11 = 0.f;

        const int m0 = by * 32;
        const int n0 = bx * 32;

        for (int kk = 0; kk < DDIM; kk += 32) {
#pragma unroll
            for (int e = 0; e < 4; e++) {
                int li = tid + e * 256;   // 0..1023
                int m = li >> 5;
                int k = li & 31;
                Ash[k][m] = embs[(m0 + m) * DDIM + kk + k];
                Bsh[k][m] = embs[(n0 + m) * DDIM + kk + k];
            }
            __syncthreads();
#pragma unroll
            for (int k = 0; k < 32; k++) {
                float2 a = *(const float2*)&Ash[k][2 * ty];
                float2 b = *(const float2*)&Bsh[k][2 * tx];
                a00 += a.x * b.x; a01 += a.x * b.y;
                a10 += a.y * b.x; a11 += a.y * b.y;
            }
            __syncthreads();
        }

        const int row0 = m0 + 2 * ty;
        const int col0 = n0 + 2 * tx;
        *(float2*)&g_dot[row0 * NROWS + col0]       = make_float2(a00, a01);
        *(float2*)&g_dot[(row0 + 1) * NROWS + col0] = make_float2(a10, a11);

        // Diagonal tiles: emit inverse norms (a00 = d[r][r], a11 = d[r+1][r+1])
        if (bx == by && tx == ty) {
            g_inv[row0]     = 1.0f / fmaxf(sqrtf(a00), 1e-8f);
            g_inv[row0 + 1] = 1.0f / fmaxf(sqrtf(a11), 1e-8f);
        }

        if (bid == 0) {
            // Dtype probe: odd int32 positions within the first 2048 bytes.
            // int64 layout -> all zero (high words of values in [0,64)).
            // int32 layout -> real class IDs, essentially never all zero.
            __shared__ int fl;
            if (tid == 0) { fl = 0; *out = 0.0f; }
            __syncthreads();
            if (((const int*)idxraw)[2 * tid + 1] != 0) atomicOr(&fl, 1);
            __syncthreads();
            if (tid == 0) g_idx32 = fl;
        }
    }

    // =================== Device-wide barrier ===================
    __syncthreads();
    __threadfence();                      // publish g_dot / g_inv / g_idx32 / *out
    if (tid == 0) {
        atomicAdd(&g_bar, 1);
        while (*(volatile int*)&g_bar < UPPER_TILES) { }
    }
    __syncthreads();
    __threadfence();                      // acquire other blocks' writes

    // ======================= Phase 2: triplet =======================
    if (bid < 64) {
        const int w    = tid >> 5;        // warp 0..7
        const int lane = tid & 31;

        __shared__ float s_inv[NROWS];
        __shared__ int   s_cls[NROWS];
        __shared__ float s_pos[8][32];    // positives per anchor (~4 expected)
        __shared__ float s_wsum[8];

        const int is32 = g_idx32;
        const int* __restrict__ i32 = (const int*)idxraw;
        const long long* __restrict__ i64 = (const long long*)idxraw;

#pragma unroll
        for (int e = 0; e < 2; e++) {
            int r = tid + e * 256;
            s_inv[r] = g_inv[r];                       // coalesced
            s_cls[r] = is32 ? i32[r] : (int)i64[r];    // coalesced
        }
        __syncthreads();

        const int i = bid * 8 + w;        // anchor (work uniform: slot loop fixed 16)
        const int   ci   = s_cls[i];
        const float invi = s_inv[i];
        const float* __restrict__ rowi = &g_dot[i * NROWS];

        // Fill register slots + compact positives. Uniform 16 iterations,
        // every lane participates in every ballot (no divergence hazard).
        float a[16];
        int np = 0;
#pragma unroll
        for (int slot = 0; slot < 16; slot++) {
            int j = i + 1 + lane + slot * 32;
            bool valid = (j < NROWS);
            float c = 0.0f;
            bool match = false;
            if (valid) {
                c = rowi[j] * invi * s_inv[j];
                match = (s_cls[j] == ci);
            }
            unsigned mask = __ballot_sync(0xffffffffu, match);
            if (match) {
                int off = np + __popc(mask & ((1u << lane) - 1u));
                if (off < 32) s_pos[w][off] = c;
            }
            np += __popc(mask);
            a[slot] = (valid && !match) ? (c + 1.0f) : -1e30f;  // sentinel -> 0
        }
        if (np > 32) np = 32;             // capacity guard (expected np ~ 4)
        __syncwarp();

        // Hot loop: np broadcast-LDS reads, 16 unrolled register fmax each.
        float s0 = 0.f, s1 = 0.f;
        for (int p = 0; p < np; p++) {
            float bp = s_pos[w][p];
#pragma unroll
            for (int slot = 0; slot < 16; slot += 2) {
                s0 += fmaxf(a[slot]     - bp, 0.0f);
                s1 += fmaxf(a[slot + 1] - bp, 0.0f);
            }
        }
        float s = s0 + s1;

#pragma unroll
        for (int o = 16; o; o >>= 1) s += __shfl_xor_sync(0xffffffffu, s, o);
        if (lane == 0) s_wsum[w] = s;
        __syncthreads();

        if (tid < 8) {
            float v = s_wsum[tid];
#pragma unroll
            for (int o = 4; o; o >>= 1) v += __shfl_xor_sync(0xffu, v, o);
            if (tid == 0) atomicAdd(out, v);   // one atomic per block (64 total)
        }
    }

    // ============ Reset counters for next graph replay ============
    // Every block increments g_done only after it has exited the spin, so
    // the 136th finisher can safely zero both counters.
    __syncthreads();
    if (tid == 0) {
        int d = atomicAdd(&g_done, 1);
        if (d == UPPER_TILES - 1) {
            g_bar  = 0;
            g_done = 0;
            __threadfence();
        }
    }
}

extern "C" void kernel_launch(void* const* d_in, const int* in_sizes, int n_in,
                              void* d_out, int out_size) {
    const float* embs = (const float*)d_in[0];
    const void*  indices = d_in[1];
    float* out = (float*)d_out;

    fused_kernel<<<UPPER_TILES, 256>>>(embs, indices, out);
}